// round 1
// baseline (speedup 1.0000x reference)
#include <cuda_runtime.h>
#include <math.h>

#define BATCH 32
#define TLEN  512
#define INDIM 128
#define RES   2048
#define OUTD  64
#define NWIN  128
#define MROWS (BATCH*NWIN)   /* 4096  reservoir rows (b,w) */
#define NROWS (BATCH*TLEN)   /* 16384 time rows (b,t)      */

/* ---------------- scratch (device globals; no allocations) ---------------- */
__device__ float g_inproj[NROWS * RES];  /* input @ W_in, per (b,t)  128 MB */
__device__ float g_S0[MROWS * RES];      /* state ping                 32 MB */
__device__ float g_S1[MROWS * RES];      /* state pong                 32 MB */
__device__ float g_rs[NROWS * RES];      /* reservoir states output   128 MB */
__device__ float g_A[BATCH * TLEN * TLEN]; /* gram matrices            32 MB */
__device__ float g_Z[BATCH * TLEN * OUTD]; /* solve result              4 MB */

/* =================== K1: inproj = input(16384x128) @ W_in(128x2048) ======= */
__global__ __launch_bounds__(256) void inproj_kernel(
    const float* __restrict__ X, const float* __restrict__ Win)
{
    __shared__ float As[16][132];
    __shared__ float Bs[16][132];
    const int row0 = blockIdx.y * 128, col0 = blockIdx.x * 128;
    const int tid = threadIdx.x;
    const int aRow = tid >> 2, aCol = (tid & 3) * 4;
    const int bRow = tid >> 5, bCol = (tid & 31) * 4;
    const int ty = tid >> 4, tx = tid & 15;
    float acc[8][8] = {};
    for (int k0 = 0; k0 < INDIM; k0 += 16) {
        float4 a0 = *(const float4*)&X[(row0 + aRow) * INDIM + k0 + aCol];
        float4 a1 = *(const float4*)&X[(row0 + aRow + 64) * INDIM + k0 + aCol];
        As[aCol + 0][aRow] = a0.x; As[aCol + 1][aRow] = a0.y;
        As[aCol + 2][aRow] = a0.z; As[aCol + 3][aRow] = a0.w;
        As[aCol + 0][aRow + 64] = a1.x; As[aCol + 1][aRow + 64] = a1.y;
        As[aCol + 2][aRow + 64] = a1.z; As[aCol + 3][aRow + 64] = a1.w;
        *(float4*)&Bs[bRow][bCol]     = *(const float4*)&Win[(k0 + bRow) * RES + col0 + bCol];
        *(float4*)&Bs[bRow + 8][bCol] = *(const float4*)&Win[(k0 + bRow + 8) * RES + col0 + bCol];
        __syncthreads();
        #pragma unroll
        for (int k = 0; k < 16; k++) {
            float fa[8], fb[8];
            *(float4*)&fa[0] = *(const float4*)&As[k][ty * 8];
            *(float4*)&fa[4] = *(const float4*)&As[k][ty * 8 + 4];
            *(float4*)&fb[0] = *(const float4*)&Bs[k][tx * 8];
            *(float4*)&fb[4] = *(const float4*)&Bs[k][tx * 8 + 4];
            #pragma unroll
            for (int i = 0; i < 8; i++)
                #pragma unroll
                for (int j = 0; j < 8; j++)
                    acc[i][j] += fa[i] * fb[j];
        }
        __syncthreads();
    }
    #pragma unroll
    for (int i = 0; i < 8; i++)
        #pragma unroll
        for (int j = 0; j < 8; j++)
            g_inproj[(row0 + ty * 8 + i) * RES + col0 + tx * 8 + j] = acc[i][j];
}

/* =================== K2a: step s=0 (state was zero) ======================= */
__global__ __launch_bounds__(256) void init0_kernel()
{
    int idx = blockIdx.x * 256 + threadIdx.x;   /* over 4096*2048 */
    int row = idx >> 11, q = idx & 2047;
    int b = row >> 7, w = row & 127;
    int t = 4 * w - 2;
    float v = 0.f;
    if (t >= 0) v = 0.3f * sinf(g_inproj[((b << 9) + t) * RES + q]);
    g_S0[idx] = v;
}

/* =========== K2: fused step: Snew = .7*Sold + .3*sin(Sold@Wres + u) ======= */
__global__ __launch_bounds__(256) void step_kernel(
    const float* __restrict__ Wres, int s, int flip)
{
    const float* __restrict__ Sold = flip ? g_S1 : g_S0;
    float* __restrict__ Snew       = flip ? g_S0 : g_S1;
    __shared__ float As[16][132];
    __shared__ float Bs[16][132];
    const int row0 = blockIdx.y * 128, col0 = blockIdx.x * 128;
    const int tid = threadIdx.x;
    const int aRow = tid >> 2, aCol = (tid & 3) * 4;
    const int bRow = tid >> 5, bCol = (tid & 31) * 4;
    const int ty = tid >> 4, tx = tid & 15;
    float acc[8][8] = {};
    for (int k0 = 0; k0 < RES; k0 += 16) {
        float4 a0 = *(const float4*)&Sold[(row0 + aRow) * RES + k0 + aCol];
        float4 a1 = *(const float4*)&Sold[(row0 + aRow + 64) * RES + k0 + aCol];
        As[aCol + 0][aRow] = a0.x; As[aCol + 1][aRow] = a0.y;
        As[aCol + 2][aRow] = a0.z; As[aCol + 3][aRow] = a0.w;
        As[aCol + 0][aRow + 64] = a1.x; As[aCol + 1][aRow + 64] = a1.y;
        As[aCol + 2][aRow + 64] = a1.z; As[aCol + 3][aRow + 64] = a1.w;
        *(float4*)&Bs[bRow][bCol]     = *(const float4*)&Wres[(k0 + bRow) * RES + col0 + bCol];
        *(float4*)&Bs[bRow + 8][bCol] = *(const float4*)&Wres[(k0 + bRow + 8) * RES + col0 + bCol];
        __syncthreads();
        #pragma unroll
        for (int k = 0; k < 16; k++) {
            float fa[8], fb[8];
            *(float4*)&fa[0] = *(const float4*)&As[k][ty * 8];
            *(float4*)&fa[4] = *(const float4*)&As[k][ty * 8 + 4];
            *(float4*)&fb[0] = *(const float4*)&Bs[k][tx * 8];
            *(float4*)&fb[4] = *(const float4*)&Bs[k][tx * 8 + 4];
            #pragma unroll
            for (int i = 0; i < 8; i++)
                #pragma unroll
                for (int j = 0; j < 8; j++)
                    acc[i][j] += fa[i] * fb[j];
        }
        __syncthreads();
    }
    /* epilogue: leaky sin update; write Snew, and rs for s>=2 */
    #pragma unroll
    for (int i = 0; i < 8; i++) {
        int row = row0 + ty * 8 + i;
        int b = row >> 7, w = row & 127;
        int t = 4 * w + s - 2;                 /* also the rs time index */
        const float* up = (t >= 0) ? &g_inproj[((b << 9) + t) * RES] : 0;
        float* rsp = (s >= 2) ? &g_rs[((b << 9) + t) * RES] : 0;
        #pragma unroll
        for (int j = 0; j < 8; j++) {
            int col = col0 + tx * 8 + j;
            float u = up ? up[col] : 0.f;
            float v = 0.7f * Sold[row * RES + col] + 0.3f * sinf(acc[i][j] + u);
            Snew[row * RES + col] = v;
            if (rsp) rsp[col] = v;
        }
    }
}

/* ============ K3: A[b] = Xb Xb^T + 1 + reg*I  (NT gram, 512x512xK2048) ==== */
__global__ __launch_bounds__(256) void gram_kernel(const float* __restrict__ lam)
{
    const int b = blockIdx.z;
    const float* __restrict__ X = g_rs + (size_t)b * TLEN * RES;
    __shared__ float As[16][132];
    __shared__ float Bs[16][132];
    const int i0 = blockIdx.y * 128, j0 = blockIdx.x * 128;
    const int tid = threadIdx.x;
    const int aRow = tid >> 2, aCol = (tid & 3) * 4;
    const int ty = tid >> 4, tx = tid & 15;
    float acc[8][8] = {};
    for (int k0 = 0; k0 < RES; k0 += 16) {
        float4 a0 = *(const float4*)&X[(i0 + aRow) * RES + k0 + aCol];
        float4 a1 = *(const float4*)&X[(i0 + aRow + 64) * RES + k0 + aCol];
        As[aCol + 0][aRow] = a0.x; As[aCol + 1][aRow] = a0.y;
        As[aCol + 2][aRow] = a0.z; As[aCol + 3][aRow] = a0.w;
        As[aCol + 0][aRow + 64] = a1.x; As[aCol + 1][aRow + 64] = a1.y;
        As[aCol + 2][aRow + 64] = a1.z; As[aCol + 3][aRow + 64] = a1.w;
        float4 b0 = *(const float4*)&X[(j0 + aRow) * RES + k0 + aCol];
        float4 b1 = *(const float4*)&X[(j0 + aRow + 64) * RES + k0 + aCol];
        Bs[aCol + 0][aRow] = b0.x; Bs[aCol + 1][aRow] = b0.y;
        Bs[aCol + 2][aRow] = b0.z; Bs[aCol + 3][aRow] = b0.w;
        Bs[aCol + 0][aRow + 64] = b1.x; Bs[aCol + 1][aRow + 64] = b1.y;
        Bs[aCol + 2][aRow + 64] = b1.z; Bs[aCol + 3][aRow + 64] = b1.w;
        __syncthreads();
        #pragma unroll
        for (int k = 0; k < 16; k++) {
            float fa[8], fb[8];
            *(float4*)&fa[0] = *(const float4*)&As[k][ty * 8];
            *(float4*)&fa[4] = *(const float4*)&As[k][ty * 8 + 4];
            *(float4*)&fb[0] = *(const float4*)&Bs[k][tx * 8];
            *(float4*)&fb[4] = *(const float4*)&Bs[k][tx * 8 + 4];
            #pragma unroll
            for (int i = 0; i < 8; i++)
                #pragma unroll
                for (int j = 0; j < 8; j++)
                    acc[i][j] += fa[i] * fb[j];
        }
        __syncthreads();
    }
    float l = lam[0];
    float reg = log1pf(expf(l));   /* softplus */
    float* Ab = g_A + (size_t)b * TLEN * TLEN;
    #pragma unroll
    for (int i = 0; i < 8; i++)
        #pragma unroll
        for (int j = 0; j < 8; j++) {
            int gi = i0 + ty * 8 + i, gj = j0 + tx * 8 + j;
            float v = acc[i][j] + 1.0f;      /* ones-column outer product */
            if (gi == gj) v += reg;
            Ab[gi * TLEN + gj] = v;
        }
}

/* ============ K4: blocked Cholesky, NB=64, one block per batch ============ */
__global__ __launch_bounds__(256) void chol_panel_kernel(int p)
{
    const int b = blockIdx.x;
    float* Ab = g_A + (size_t)b * TLEN * TLEN;
    const int jb = p * 64;
    __shared__ float L11[64][65];
    const int tid = threadIdx.x;
    for (int idx = tid; idx < 64 * 64; idx += 256) {
        int r = idx >> 6, c = idx & 63;
        L11[r][c] = Ab[(jb + r) * TLEN + jb + c];
    }
    __syncthreads();
    for (int k = 0; k < 64; k++) {
        if (tid == 0) L11[k][k] = sqrtf(L11[k][k]);
        __syncthreads();
        if (tid > k && tid < 64) L11[tid][k] /= L11[k][k];
        __syncthreads();
        for (int idx = tid; idx < 64 * 64; idx += 256) {
            int r = idx >> 6, c = idx & 63;
            if (r > k && c > k && c <= r) L11[r][c] -= L11[r][k] * L11[c][k];
        }
        __syncthreads();
    }
    for (int idx = tid; idx < 64 * 64; idx += 256) {
        int r = idx >> 6, c = idx & 63;
        if (c <= r) Ab[(jb + r) * TLEN + jb + c] = L11[r][c];
    }
    __syncthreads();
    /* panel solve: A21 <- A21 * L11^{-T} */
    const int m = TLEN - jb - 64;
    for (int r = tid; r < m; r += 256) {
        int i = jb + 64 + r;
        float a[64];
        #pragma unroll
        for (int c = 0; c < 64; c++) a[c] = Ab[i * TLEN + jb + c];
        #pragma unroll
        for (int k = 0; k < 64; k++) {
            float s = a[k];
            #pragma unroll
            for (int q = 0; q < k; q++) s -= a[q] * L11[k][q];
            a[k] = s / L11[k][k];
        }
        #pragma unroll
        for (int c = 0; c < 64; c++) Ab[i * TLEN + jb + c] = a[c];
    }
}

__global__ __launch_bounds__(256) void chol_update_kernel(int p)
{
    const int jb = p * 64 + 64;
    int idx = blockIdx.x;
    int ti = 0;
    while ((ti + 1) * (ti + 2) / 2 <= idx) ti++;
    int tj = idx - ti * (ti + 1) / 2;
    const int b = blockIdx.y;
    float* Ab = g_A + (size_t)b * TLEN * TLEN;
    const int r0 = jb + ti * 64, c0 = jb + tj * 64;
    __shared__ float La[64][65], Lb[64][65];
    const int tid = threadIdx.x;
    for (int q = tid; q < 64 * 64; q += 256) {
        int r = q >> 6, c = q & 63;
        La[r][c] = Ab[(r0 + r) * TLEN + p * 64 + c];
        Lb[r][c] = Ab[(c0 + r) * TLEN + p * 64 + c];
    }
    __syncthreads();
    const int tx = tid & 15, ty = tid >> 4;
    float acc[4][4] = {};
    #pragma unroll
    for (int k = 0; k < 64; k++) {
        float ar[4], bc[4];
        #pragma unroll
        for (int i = 0; i < 4; i++) ar[i] = La[ty * 4 + i][k];
        #pragma unroll
        for (int j = 0; j < 4; j++) bc[j] = Lb[tx * 4 + j][k];
        #pragma unroll
        for (int i = 0; i < 4; i++)
            #pragma unroll
            for (int j = 0; j < 4; j++)
                acc[i][j] += ar[i] * bc[j];
    }
    #pragma unroll
    for (int i = 0; i < 4; i++)
        #pragma unroll
        for (int j = 0; j < 4; j++)
            Ab[(r0 + ty * 4 + i) * TLEN + c0 + tx * 4 + j] -= acc[i][j];
}

/* ============ K5: triangular solves, 64 RHS in registers ================== */
__global__ __launch_bounds__(512) void solve_kernel(const float* __restrict__ Y)
{
    const int b = blockIdx.x;
    const int i = threadIdx.x;
    const float* __restrict__ Ab = g_A + (size_t)b * TLEN * TLEN;
    float acc[OUTD];
    #pragma unroll
    for (int o = 0; o < OUTD; o++) acc[o] = Y[((size_t)b * TLEN + i) * OUTD + o];
    __shared__ float zrow[OUTD];
    /* forward: L w = y */
    for (int j = 0; j < TLEN; j++) {
        if (i == j) {
            float dinv = 1.f / Ab[j * TLEN + j];
            #pragma unroll
            for (int o = 0; o < OUTD; o++) { acc[o] *= dinv; zrow[o] = acc[o]; }
        }
        __syncthreads();
        if (i > j) {
            float lij = Ab[i * TLEN + j];
            #pragma unroll
            for (int o = 0; o < OUTD; o++) acc[o] -= lij * zrow[o];
        }
        __syncthreads();
    }
    /* backward: L^T z = w */
    for (int j = TLEN - 1; j >= 0; j--) {
        if (i == j) {
            float dinv = 1.f / Ab[j * TLEN + j];
            #pragma unroll
            for (int o = 0; o < OUTD; o++) { acc[o] *= dinv; zrow[o] = acc[o]; }
        }
        __syncthreads();
        if (i < j) {
            float lji = Ab[j * TLEN + i];   /* coalesced */
            #pragma unroll
            for (int o = 0; o < OUTD; o++) acc[o] -= lji * zrow[o];
        }
        __syncthreads();
    }
    #pragma unroll
    for (int o = 0; o < OUTD; o++) g_Z[((size_t)b * TLEN + i) * OUTD + o] = acc[o];
}

/* ============ K6: W = Xb^T Z  (2048 x 64, K=512) ========================== */
__global__ __launch_bounds__(256) void wout_kernel(float* __restrict__ out)
{
    const int b = blockIdx.y;
    const float* __restrict__ X = g_rs + (size_t)b * TLEN * RES; /* X[n][d] */
    const float* __restrict__ Zb = g_Z + (size_t)b * TLEN * OUTD;
    const int d0 = blockIdx.x * 128;
    __shared__ float As[16][132];  /* As[k][d] */
    __shared__ float Bs[16][68];   /* Bs[k][o] */
    const int tid = threadIdx.x;
    const int lr = tid >> 4, lc = (tid & 15) * 4;
    const int ty = tid >> 4, tx = tid & 15;
    float acc[8][4] = {};
    for (int k0 = 0; k0 < TLEN; k0 += 16) {
        *(float4*)&As[lr][lc]      = *(const float4*)&X[(k0 + lr) * RES + d0 + lc];
        *(float4*)&As[lr][lc + 64] = *(const float4*)&X[(k0 + lr) * RES + d0 + lc + 64];
        *(float4*)&Bs[lr][lc]      = *(const float4*)&Zb[(k0 + lr) * OUTD + lc];
        __syncthreads();
        #pragma unroll
        for (int k = 0; k < 16; k++) {
            float fa[8], fb[4];
            *(float4*)&fa[0] = *(const float4*)&As[k][ty * 8];
            *(float4*)&fa[4] = *(const float4*)&As[k][ty * 8 + 4];
            *(float4*)&fb[0] = *(const float4*)&Bs[k][tx * 4];
            #pragma unroll
            for (int i = 0; i < 8; i++)
                #pragma unroll
                for (int j = 0; j < 4; j++)
                    acc[i][j] += fa[i] * fb[j];
        }
        __syncthreads();
    }
    #pragma unroll
    for (int i = 0; i < 8; i++)
        #pragma unroll
        for (int j = 0; j < 4; j++)
            out[((size_t)b * RES + d0 + ty * 8 + i) * OUTD + tx * 4 + j] = acc[i][j];
}

__global__ void bias_kernel(float* __restrict__ out)
{
    const int b = blockIdx.x, o = threadIdx.x;   /* 64 threads */
    float s = 0.f;
    for (int n = 0; n < TLEN; n++) s += g_Z[((size_t)b * TLEN + n) * OUTD + o];
    out[(size_t)BATCH * RES * OUTD + b * OUTD + o] = s;
}

/* ======================= launch ======================= */
extern "C" void kernel_launch(void* const* d_in, const int* in_sizes, int n_in,
                              void* d_out, int out_size)
{
    const float* input  = (const float*)d_in[0];
    const float* target = (const float*)d_in[1];
    const float* W_res  = (const float*)d_in[2];
    const float* W_in   = (const float*)d_in[3];
    const float* lam    = (const float*)d_in[4];
    float* out = (float*)d_out;

    /* 1. input projection: (16384x128)@(128x2048) */
    inproj_kernel<<<dim3(RES / 128, NROWS / 128), 256>>>(input, W_in);

    /* 2. reservoir: step 0 special-cased (state=0), then 5 fused GEMM steps */
    init0_kernel<<<(MROWS * RES) / 256, 256>>>();
    int flip = 0;                                  /* S0 currently holds state */
    for (int s = 1; s <= 5; s++) {
        step_kernel<<<dim3(RES / 128, MROWS / 128), 256>>>(W_res, s, flip);
        flip ^= 1;
    }

    /* 3. gram matrices */
    gram_kernel<<<dim3(4, 4, BATCH), 256>>>(lam);

    /* 4. batched blocked Cholesky */
    for (int p = 0; p < 8; p++) {
        chol_panel_kernel<<<BATCH, 256>>>(p);
        if (p < 7) {
            int mt = 7 - p;
            int tiles = mt * (mt + 1) / 2;
            chol_update_kernel<<<dim3(tiles, BATCH), 256>>>(p);
        }
    }

    /* 5. triangular solves (64 RHS) */
    solve_kernel<<<BATCH, 512>>>(target);

    /* 6. readout weights + bias */
    wout_kernel<<<dim3(RES / 128, BATCH), 256>>>(out);
    bias_kernel<<<BATCH, 64>>>(out);

    (void)in_sizes; (void)n_in; (void)out_size;
}

// round 3
// speedup vs baseline: 1.2705x; 1.2705x over previous
#include <cuda_runtime.h>
#include <math.h>
#include <stdint.h>

#define BATCH 32
#define TLEN  512
#define INDIM 128
#define RES   2048
#define OUTD  64
#define NWIN  128
#define MROWS (BATCH*NWIN)   /* 4096  reservoir rows (b,w) */
#define NROWS (BATCH*TLEN)   /* 16384 time rows (b,t)      */

/* ---------------- scratch (device globals; no allocations) ---------------- */
__device__ float g_inproj[NROWS * RES];    /* input @ W_in          128 MB */
__device__ float g_S0[MROWS * RES];        /* state ping             32 MB */
__device__ float g_S1[MROWS * RES];        /* state pong             32 MB */
__device__ float g_rs[NROWS * RES];        /* reservoir states      128 MB */
__device__ float g_A[BATCH * TLEN * TLEN]; /* gram matrices          32 MB */
__device__ float g_Z[BATCH * TLEN * OUTD]; /* solve result            4 MB */
__device__ float g_WresT[RES * RES];       /* W_res transposed       16 MB */
__device__ float g_WinT[RES * INDIM];      /* W_in transposed         1 MB */

/* ====================== helpers ====================== */
__device__ __forceinline__ uint32_t smem_u32(const void* p) {
    uint32_t a;
    asm("{ .reg .u64 t; cvta.to.shared.u64 t, %1; cvt.u32.u64 %0, t; }" : "=r"(a) : "l"(p));
    return a;
}

__device__ __forceinline__ void cpasync16(uint32_t dst, const void* src) {
    asm volatile("cp.async.cg.shared.global [%0], [%1], 16;" :: "r"(dst), "l"(src));
}
__device__ __forceinline__ void cp_commit() {
    asm volatile("cp.async.commit_group;" ::: "memory");
}
__device__ __forceinline__ void cp_wait1() {
    asm volatile("cp.async.wait_group 1;" ::: "memory");
}
__device__ __forceinline__ void cp_wait0() {
    asm volatile("cp.async.wait_group 0;" ::: "memory");
}

/* m16n8k8 tf32 mma: D += A*B, row.col */
__device__ __forceinline__ void mma1688(float* d, const uint32_t* a, const uint32_t* b) {
    asm volatile(
        "mma.sync.aligned.m16n8k8.row.col.f32.tf32.tf32.f32 "
        "{%0,%1,%2,%3},{%4,%5,%6,%7},{%8,%9},{%0,%1,%2,%3};"
        : "+f"(d[0]), "+f"(d[1]), "+f"(d[2]), "+f"(d[3])
        : "r"(a[0]), "r"(a[1]), "r"(a[2]), "r"(a[3]), "r"(b[0]), "r"(b[1]));
}

__device__ __forceinline__ void split_tf32(float f, uint32_t& hi, uint32_t& lo) {
    uint32_t u = __float_as_uint(f) & 0xFFFFE000u;
    hi = u;
    lo = __float_as_uint(f - __uint_as_float(u));
}

/* ============ generic tf32x3 GEMM kernel (mma.sync HMMA path) =============
   C[row0+i][col0+j] = sum_k A[row0+i][k] * B[col0+j][k]   (A·B^T, K-major)
   mode 0: reservoir step  (A=Sold, B=WresT, fused leaky-sin epilogue)
   mode 1: gram            (A=B=rs batch slice, +1 +reg*I epilogue)
   mode 2: inproj          (A=input, B=WinT, plain store)                  */
#define TCPAD 36
#define SMEM_DYN (2 * 2 * 128 * TCPAD * 4)   /* 73728 B */

__global__ __launch_bounds__(512, 1) void tc_kernel(
    int mode, const float* __restrict__ Xin, int s, int flip,
    const float* __restrict__ lam)
{
    extern __shared__ float sm[];
    float* As = sm;                    /* [2][128][TCPAD] */
    float* Bs = sm + 2 * 128 * TCPAD;  /* [2][128][TCPAD] */
    const uint32_t As_u = smem_u32(As), Bs_u = smem_u32(Bs);

    const int tid = threadIdx.x;
    const int wid = tid >> 5, lane = tid & 31;
    const int gid = lane >> 2, tig = lane & 3;
    const int warpM = wid >> 2, warpN = wid & 3;
    const int rowBase = warpM * 32, colBase = warpN * 32;
    const int row0 = blockIdx.y * 128, col0 = blockIdx.x * 128;

    const float* Ab; const float* Bb; int K;
    if (mode == 0)      { Ab = flip ? g_S1 : g_S0; Bb = g_WresT; K = RES; }
    else if (mode == 1) { const float* base = g_rs + (size_t)blockIdx.z * TLEN * RES;
                          Ab = base; Bb = base; K = RES; }
    else                { Ab = Xin; Bb = g_WinT; K = INDIM; }
    const int nIter = K >> 5;

    float acc[2][4][4] = {};

    /* ---- chunk loader: 128 rows x 32 k into buf (A and B) ---- */
    auto load_chunk = [&](int it, int buf) {
        const int k0 = it << 5;
        #pragma unroll
        for (int q = 0; q < 2; q++) {
            int idx = tid + q * 512;             /* 1024 float4 slots */
            int r = idx >> 3, c4 = idx & 7;
            uint32_t soff = ((uint32_t)(buf * 128 + r) * TCPAD + c4 * 4) * 4;
            cpasync16(As_u + soff, &Ab[(size_t)(row0 + r) * K + k0 + c4 * 4]);
            cpasync16(Bs_u + soff, &Bb[(size_t)(col0 + r) * K + k0 + c4 * 4]);
        }
    };

    load_chunk(0, 0);
    cp_commit();

    for (int it = 0; it < nIter; ++it) {
        const int buf = it & 1;
        if (it + 1 < nIter) { load_chunk(it + 1, buf ^ 1); cp_commit(); cp_wait1(); }
        else                { cp_wait0(); }
        __syncthreads();

        const float* Ap = As + (size_t)buf * 128 * TCPAD;
        const float* Bp = Bs + (size_t)buf * 128 * TCPAD;
        #pragma unroll
        for (int k8 = 0; k8 < 4; k8++) {
            const int kk = k8 * 8 + tig;
            uint32_t ah[2][4], al[2][4], bh[4][2], bl[4][2];
            #pragma unroll
            for (int mt = 0; mt < 2; mt++) {
                int r = rowBase + mt * 16 + gid;
                split_tf32(Ap[r * TCPAD + kk],           ah[mt][0], al[mt][0]);
                split_tf32(Ap[(r + 8) * TCPAD + kk],     ah[mt][1], al[mt][1]);
                split_tf32(Ap[r * TCPAD + kk + 4],       ah[mt][2], al[mt][2]);
                split_tf32(Ap[(r + 8) * TCPAD + kk + 4], ah[mt][3], al[mt][3]);
            }
            #pragma unroll
            for (int nt = 0; nt < 4; nt++) {
                int n = colBase + nt * 8 + gid;
                split_tf32(Bp[n * TCPAD + kk],     bh[nt][0], bl[nt][0]);
                split_tf32(Bp[n * TCPAD + kk + 4], bh[nt][1], bl[nt][1]);
            }
            #pragma unroll
            for (int mt = 0; mt < 2; mt++)
                #pragma unroll
                for (int nt = 0; nt < 4; nt++) {
                    mma1688(acc[mt][nt], ah[mt], bh[nt]);
                    mma1688(acc[mt][nt], ah[mt], bl[nt]);
                    mma1688(acc[mt][nt], al[mt], bh[nt]);
                }
        }
        __syncthreads();
    }

    /* -------------------- epilogue (register -> global) -------------------- */
    float regc = 0.f;
    if (mode == 1) { float l = lam[0]; regc = log1pf(expf(l)); }
    const float* Sold = flip ? g_S1 : g_S0;
    float* Snew = flip ? g_S0 : g_S1;

    #pragma unroll
    for (int mt = 0; mt < 2; mt++)
        #pragma unroll
        for (int nt = 0; nt < 4; nt++)
            #pragma unroll
            for (int h = 0; h < 2; h++) {
                int grow = row0 + rowBase + mt * 16 + gid + h * 8;
                int col = col0 + colBase + nt * 8 + tig * 2;
                float cx = acc[mt][nt][h * 2 + 0];
                float cy = acc[mt][nt][h * 2 + 1];
                if (mode == 0) {
                    int b = grow >> 7, w = grow & 127;
                    int t = 4 * w + s - 2;
                    float2 so = *(const float2*)&Sold[(size_t)grow * RES + col];
                    float2 u = make_float2(0.f, 0.f);
                    if (t >= 0) u = *(const float2*)&g_inproj[((size_t)(b << 9) + t) * RES + col];
                    float2 v;
                    v.x = 0.7f * so.x + 0.3f * sinf(cx + u.x);
                    v.y = 0.7f * so.y + 0.3f * sinf(cy + u.y);
                    *(float2*)&Snew[(size_t)grow * RES + col] = v;
                    if (s >= 2) *(float2*)&g_rs[((size_t)(b << 9) + t) * RES + col] = v;
                } else if (mode == 1) {
                    float* Abm = g_A + (size_t)blockIdx.z * TLEN * TLEN;
                    float2 v;
                    v.x = cx + 1.0f + ((grow == col + 0) ? regc : 0.f);
                    v.y = cy + 1.0f + ((grow == col + 1) ? regc : 0.f);
                    *(float2*)&Abm[(size_t)grow * TLEN + col] = v;
                } else {
                    float2 v = make_float2(cx, cy);
                    *(float2*)&g_inproj[(size_t)grow * RES + col] = v;
                }
            }
}

/* ================= transpose: dst[c][r] = src[r][c] ======================= */
__global__ void transpose_kernel(const float* __restrict__ src, int rows, int cols, int which)
{
    float* dst = which ? g_WinT : g_WresT;
    __shared__ float t[32][33];
    int c0 = blockIdx.x * 32, r0 = blockIdx.y * 32;
    for (int j = threadIdx.y; j < 32; j += 8)
        t[j][threadIdx.x] = src[(size_t)(r0 + j) * cols + c0 + threadIdx.x];
    __syncthreads();
    for (int j = threadIdx.y; j < 32; j += 8)
        dst[(size_t)(c0 + j) * rows + r0 + threadIdx.x] = t[threadIdx.x][j];
}

/* =================== step s=0 (state was zero) ============================ */
__global__ __launch_bounds__(256) void init0_kernel()
{
    int idx = blockIdx.x * 256 + threadIdx.x;
    int row = idx >> 11, qq = idx & 2047;
    int b = row >> 7, w = row & 127;
    int t = 4 * w - 2;
    float v = 0.f;
    if (t >= 0) v = 0.3f * sinf(g_inproj[((size_t)(b << 9) + t) * RES + qq]);
    g_S0[idx] = v;
}

/* ============ blocked Cholesky, NB=64 ===================================== */
__global__ __launch_bounds__(256) void chol_panel_kernel(int p)
{
    const int b = blockIdx.x;
    float* Ab = g_A + (size_t)b * TLEN * TLEN;
    const int jb = p * 64;
    __shared__ float L11[64][65];
    const int tid = threadIdx.x;
    for (int idx = tid; idx < 64 * 64; idx += 256) {
        int r = idx >> 6, c = idx & 63;
        L11[r][c] = Ab[(jb + r) * TLEN + jb + c];
    }
    __syncthreads();
    for (int k = 0; k < 64; k++) {
        if (tid == 0) L11[k][k] = sqrtf(L11[k][k]);
        __syncthreads();
        if (tid > k && tid < 64) L11[tid][k] /= L11[k][k];
        __syncthreads();
        for (int idx = tid; idx < 64 * 64; idx += 256) {
            int r = idx >> 6, c = idx & 63;
            if (r > k && c > k && c <= r) L11[r][c] -= L11[r][k] * L11[c][k];
        }
        __syncthreads();
    }
    for (int idx = tid; idx < 64 * 64; idx += 256) {
        int r = idx >> 6, c = idx & 63;
        if (c <= r) Ab[(jb + r) * TLEN + jb + c] = L11[r][c];
    }
    __syncthreads();
    const int m = TLEN - jb - 64;
    for (int r = tid; r < m; r += 256) {
        int i = jb + 64 + r;
        float a[64];
        #pragma unroll
        for (int c = 0; c < 64; c++) a[c] = Ab[i * TLEN + jb + c];
        #pragma unroll
        for (int k = 0; k < 64; k++) {
            float sv = a[k];
            #pragma unroll
            for (int q = 0; q < k; q++) sv -= a[q] * L11[k][q];
            a[k] = sv / L11[k][k];
        }
        #pragma unroll
        for (int c = 0; c < 64; c++) Ab[i * TLEN + jb + c] = a[c];
    }
}

__global__ __launch_bounds__(256) void chol_update_kernel(int p)
{
    const int jb = p * 64 + 64;
    int idx = blockIdx.x;
    int ti = 0;
    while ((ti + 1) * (ti + 2) / 2 <= idx) ti++;
    int tj = idx - ti * (ti + 1) / 2;
    const int b = blockIdx.y;
    float* Ab = g_A + (size_t)b * TLEN * TLEN;
    const int r0 = jb + ti * 64, c0 = jb + tj * 64;
    __shared__ float La[64][65], Lb[64][65];
    const int tid = threadIdx.x;
    for (int q = tid; q < 64 * 64; q += 256) {
        int r = q >> 6, c = q & 63;
        La[r][c] = Ab[(r0 + r) * TLEN + p * 64 + c];
        Lb[r][c] = Ab[(c0 + r) * TLEN + p * 64 + c];
    }
    __syncthreads();
    const int tx = tid & 15, ty = tid >> 4;
    float acc[4][4] = {};
    #pragma unroll
    for (int k = 0; k < 64; k++) {
        float ar[4], bc[4];
        #pragma unroll
        for (int i = 0; i < 4; i++) ar[i] = La[ty * 4 + i][k];
        #pragma unroll
        for (int j = 0; j < 4; j++) bc[j] = Lb[tx * 4 + j][k];
        #pragma unroll
        for (int i = 0; i < 4; i++)
            #pragma unroll
            for (int j = 0; j < 4; j++)
                acc[i][j] += ar[i] * bc[j];
    }
    #pragma unroll
    for (int i = 0; i < 4; i++)
        #pragma unroll
        for (int j = 0; j < 4; j++)
            Ab[(r0 + ty * 4 + i) * TLEN + c0 + tx * 4 + j] -= acc[i][j];
}

/* ============ triangular solves, 64 RHS in registers ====================== */
__global__ __launch_bounds__(512) void solve_kernel(const float* __restrict__ Y)
{
    const int b = blockIdx.x;
    const int i = threadIdx.x;
    const float* __restrict__ Ab = g_A + (size_t)b * TLEN * TLEN;
    float acc[OUTD];
    #pragma unroll
    for (int o = 0; o < OUTD; o++) acc[o] = Y[((size_t)b * TLEN + i) * OUTD + o];
    __shared__ float zrow[OUTD];
    for (int j = 0; j < TLEN; j++) {
        if (i == j) {
            float dinv = 1.f / Ab[j * TLEN + j];
            #pragma unroll
            for (int o = 0; o < OUTD; o++) { acc[o] *= dinv; zrow[o] = acc[o]; }
        }
        __syncthreads();
        if (i > j) {
            float lij = Ab[i * TLEN + j];
            #pragma unroll
            for (int o = 0; o < OUTD; o++) acc[o] -= lij * zrow[o];
        }
        __syncthreads();
    }
    for (int j = TLEN - 1; j >= 0; j--) {
        if (i == j) {
            float dinv = 1.f / Ab[j * TLEN + j];
            #pragma unroll
            for (int o = 0; o < OUTD; o++) { acc[o] *= dinv; zrow[o] = acc[o]; }
        }
        __syncthreads();
        if (i < j) {
            float lji = Ab[j * TLEN + i];
            #pragma unroll
            for (int o = 0; o < OUTD; o++) acc[o] -= lji * zrow[o];
        }
        __syncthreads();
    }
    #pragma unroll
    for (int o = 0; o < OUTD; o++) g_Z[((size_t)b * TLEN + i) * OUTD + o] = acc[o];
}

/* ============ W = Xb^T Z  (2048 x 64, K=512) ============================== */
__global__ __launch_bounds__(256) void wout_kernel(float* __restrict__ out)
{
    const int b = blockIdx.y;
    const float* __restrict__ X = g_rs + (size_t)b * TLEN * RES;
    const float* __restrict__ Zb = g_Z + (size_t)b * TLEN * OUTD;
    const int d0 = blockIdx.x * 128;
    __shared__ float As2[16][132];
    __shared__ float Bs2[16][68];
    const int tid = threadIdx.x;
    const int lr = tid >> 4, lc = (tid & 15) * 4;
    const int ty = tid >> 4, tx = tid & 15;
    float acc[8][4] = {};
    for (int k0 = 0; k0 < TLEN; k0 += 16) {
        *(float4*)&As2[lr][lc]      = *(const float4*)&X[(size_t)(k0 + lr) * RES + d0 + lc];
        *(float4*)&As2[lr][lc + 64] = *(const float4*)&X[(size_t)(k0 + lr) * RES + d0 + lc + 64];
        *(float4*)&Bs2[lr][lc]      = *(const float4*)&Zb[(k0 + lr) * OUTD + lc];
        __syncthreads();
        #pragma unroll
        for (int k = 0; k < 16; k++) {
            float fa[8], fb[4];
            *(float4*)&fa[0] = *(const float4*)&As2[k][ty * 8];
            *(float4*)&fa[4] = *(const float4*)&As2[k][ty * 8 + 4];
            *(float4*)&fb[0] = *(const float4*)&Bs2[k][tx * 4];
            #pragma unroll
            for (int i = 0; i < 8; i++)
                #pragma unroll
                for (int j = 0; j < 4; j++)
                    acc[i][j] += fa[i] * fb[j];
        }
        __syncthreads();
    }
    #pragma unroll
    for (int i = 0; i < 8; i++)
        #pragma unroll
        for (int j = 0; j < 4; j++)
            out[((size_t)b * RES + d0 + ty * 8 + i) * OUTD + tx * 4 + j] = acc[i][j];
}

__global__ void bias_kernel(float* __restrict__ out)
{
    const int b = blockIdx.x, o = threadIdx.x;
    float s = 0.f;
    for (int n = 0; n < TLEN; n++) s += g_Z[((size_t)b * TLEN + n) * OUTD + o];
    out[(size_t)BATCH * RES * OUTD + b * OUTD + o] = s;
}

/* ======================= launch ======================= */
extern "C" void kernel_launch(void* const* d_in, const int* in_sizes, int n_in,
                              void* d_out, int out_size)
{
    const float* input  = (const float*)d_in[0];
    const float* target = (const float*)d_in[1];
    const float* W_res  = (const float*)d_in[2];
    const float* W_in   = (const float*)d_in[3];
    const float* lam    = (const float*)d_in[4];
    float* out = (float*)d_out;

    cudaFuncSetAttribute(tc_kernel, cudaFuncAttributeMaxDynamicSharedMemorySize, SMEM_DYN);

    /* transposes for K-major A·B^T form */
    transpose_kernel<<<dim3(RES / 32, RES / 32), dim3(32, 8)>>>(W_res, RES, RES, 0);
    transpose_kernel<<<dim3(RES / 32, INDIM / 32), dim3(32, 8)>>>(W_in, INDIM, RES, 1);

    /* 1. input projection (tensor) */
    tc_kernel<<<dim3(RES / 128, NROWS / 128), 512, SMEM_DYN>>>(2, input, 0, 0, nullptr);

    /* 2. reservoir */
    init0_kernel<<<(MROWS * RES) / 256, 256>>>();
    int flip = 0;
    for (int s = 1; s <= 5; s++) {
        tc_kernel<<<dim3(RES / 128, MROWS / 128), 512, SMEM_DYN>>>(0, nullptr, s, flip, nullptr);
        flip ^= 1;
    }

    /* 3. gram (tensor) */
    tc_kernel<<<dim3(4, 4, BATCH), 512, SMEM_DYN>>>(1, nullptr, 0, 0, lam);

    /* 4. batched blocked Cholesky */
    for (int p = 0; p < 8; p++) {
        chol_panel_kernel<<<BATCH, 256>>>(p);
        if (p < 7) {
            int mt = 7 - p;
            chol_update_kernel<<<dim3(mt * (mt + 1) / 2, BATCH), 256>>>(p);
        }
    }

    /* 5. triangular solves */
    solve_kernel<<<BATCH, 512>>>(target);

    /* 6. readout */
    wout_kernel<<<dim3(RES / 128, BATCH), 256>>>(out);
    bias_kernel<<<BATCH, 64>>>(out);

    (void)in_sizes; (void)n_in; (void)out_size;
}